// round 1
// baseline (speedup 1.0000x reference)
#include <cuda_runtime.h>

#define B_CHAIN 16384
#define S_SIDE 15
#define NATM (1 + B_CHAIN + B_CHAIN * S_SIDE)
#define GEN1_BASE (1 + B_CHAIN)

#define NCHUNK 1024
#define CHUNK 16   // B_CHAIN / NCHUNK

// Scratch (static __device__ arrays — no allocation).
// Local transforms for backbone atoms 1..B_CHAIN (row 0 unused). ~786KB, L2-resident.
__device__ __align__(16) float g_ht0[(B_CHAIN + 1) * 12];
// Global transforms for backbone atoms 1..B_CHAIN (parents of side chains).
__device__ __align__(16) float g_hg0[(B_CHAIN + 1) * 12];

// Affine 3x4: m[0..8] row-major rotation, m[9..11] translation.
// c = a * b  (safe when c aliases a; b must be distinct)
__device__ __forceinline__ void aff_mul(const float a[12], const float b[12], float c[12]) {
#pragma unroll
    for (int i = 0; i < 3; i++) {
        float a0 = a[i * 3 + 0], a1 = a[i * 3 + 1], a2 = a[i * 3 + 2];
        float t  = a[9 + i];
        c[i * 3 + 0] = a0 * b[0] + a1 * b[3] + a2 * b[6];
        c[i * 3 + 1] = a0 * b[1] + a1 * b[4] + a2 * b[7];
        c[i * 3 + 2] = a0 * b[2] + a1 * b[5] + a2 * b[8];
        c[9 + i]     = a0 * b[9] + a1 * b[10] + a2 * b[11] + t;
    }
}

__device__ __forceinline__ void aff_identity(float m[12]) {
#pragma unroll
    for (int k = 0; k < 12; k++) m[k] = 0.0f;
    m[0] = m[4] = m[8] = 1.0f;
}

// ht_bond = Rx(p) * Rz(t) * T(d,0,0) * Rx(c), collapsed closed form.
__device__ __forceinline__ void make_bond(float p, float t, float d, float c, float m[12]) {
    float sp, cp, st, ct, sc, cc;
    sincosf(p, &sp, &cp);
    sincosf(t, &st, &ct);
    sincosf(c, &sc, &cc);
    m[0] = ct;        m[1] = -st * cc;               m[2] = st * sc;
    m[3] = cp * st;   m[4] = cp * ct * cc - sp * sc; m[5] = -cp * ct * sc - sp * cc;
    m[6] = sp * st;   m[7] = sp * ct * cc + cp * sc; m[8] = -sp * ct * sc + cp * cc;
    m[9] = ct * d;    m[10] = cp * st * d;           m[11] = sp * st * d;
}

// ht for atom given its 4 dofs. Atom 1 is jump-type with d4=d5=0:
//   T(d0,d1,d2) * Rx(d3). All other atoms (>=2) are bond-type.
__device__ __forceinline__ void make_ht(int atom, float4 dv, float m[12]) {
    if (atom == 1) {
        float sc, cc;
        sincosf(dv.w, &sc, &cc);
        m[0] = 1.f; m[1] = 0.f; m[2] = 0.f;
        m[3] = 0.f; m[4] = cc;  m[5] = -sc;
        m[6] = 0.f; m[7] = sc;  m[8] = cc;
        m[9] = dv.x; m[10] = dv.y; m[11] = dv.z;
    } else {
        make_bond(dv.x, dv.y, dv.z, dv.w, m);
    }
}

__device__ __forceinline__ void store12(float* dst, const float m[12]) {
    float4* d4 = (float4*)dst;
    d4[0] = make_float4(m[0], m[1], m[2], m[3]);
    d4[1] = make_float4(m[4], m[5], m[6], m[7]);
    d4[2] = make_float4(m[8], m[9], m[10], m[11]);
}

__device__ __forceinline__ void load12(const float* src, float m[12]) {
    const float4* s4 = (const float4*)src;
    float4 a = s4[0], b = s4[1], c = s4[2];
    m[0] = a.x; m[1] = a.y; m[2] = a.z; m[3] = a.w;
    m[4] = b.x; m[5] = b.y; m[6] = b.z; m[7] = b.w;
    m[8] = c.x; m[9] = c.y; m[10] = c.z; m[11] = c.w;
}

// ---------------------------------------------------------------------------
// K1: local ht for backbone atoms 1..B_CHAIN -> g_ht0 (L2-resident scratch)
// ---------------------------------------------------------------------------
__global__ void k1_backbone_ht(const float* __restrict__ dofs) {
    int i = blockIdx.x * blockDim.x + threadIdx.x;
    if (i >= B_CHAIN) return;
    int atom = i + 1;
    float4 dv = ((const float4*)dofs)[atom - 1];
    float m[12];
    make_ht(atom, dv, m);
    store12(g_ht0 + atom * 12, m);
}

// ---------------------------------------------------------------------------
// K2: backbone prefix scan, single block of NCHUNK threads.
//   pass1: serial chunk products -> shared (SoA, conflict-free)
//   Kogge-Stone inclusive scan over NCHUNK chunk totals (10 steps)
//   pass2: re-walk chunk with exclusive prefix, write g_hg0 + scattered coords
// ---------------------------------------------------------------------------
__global__ void __launch_bounds__(NCHUNK) k2_backbone_scan(
    const int* __restrict__ kin_id, float* __restrict__ out) {
    __shared__ float s[12 * NCHUNK];   // 48KB, component-major: s[k*NCHUNK + t]
    int t = threadIdx.x;
    int base = 1 + t * CHUNK;

    // pass 1: chunk product
    float P[12];
    load12(g_ht0 + base * 12, P);
#pragma unroll 4
    for (int j = 1; j < CHUNK; j++) {
        float M[12], T[12];
        load12(g_ht0 + (base + j) * 12, M);
        aff_mul(P, M, T);
#pragma unroll
        for (int k = 0; k < 12; k++) P[k] = T[k];
    }
#pragma unroll
    for (int k = 0; k < 12; k++) s[k * NCHUNK + t] = P[k];
    __syncthreads();

    // Kogge-Stone inclusive scan (left-to-right products)
    for (int d = 1; d < NCHUNK; d <<= 1) {
        float L[12];
        bool act = (t >= d);
        if (act) {
#pragma unroll
            for (int k = 0; k < 12; k++) L[k] = s[k * NCHUNK + (t - d)];
        }
        __syncthreads();
        if (act) {
            float T[12];
            aff_mul(L, P, T);
#pragma unroll
            for (int k = 0; k < 12; k++) { P[k] = T[k]; s[k * NCHUNK + t] = T[k]; }
        }
        __syncthreads();
    }

    // exclusive prefix for this chunk
    float G[12];
    if (t == 0) {
        aff_identity(G);
    } else {
#pragma unroll
        for (int k = 0; k < 12; k++) G[k] = s[k * NCHUNK + (t - 1)];
    }

    // pass 2: global transforms + scattered coordinates
#pragma unroll 4
    for (int j = 0; j < CHUNK; j++) {
        int atom = base + j;
        float M[12], T[12];
        load12(g_ht0 + atom * 12, M);
        aff_mul(G, M, T);
#pragma unroll
        for (int k = 0; k < 12; k++) G[k] = T[k];
        store12(g_hg0 + atom * 12, G);
        int kid = kin_id[atom];
        out[kid * 3 + 0] = G[9];
        out[kid * 3 + 1] = G[10];
        out[kid * 3 + 2] = G[11];
    }
}

// ---------------------------------------------------------------------------
// K3: side chains. One thread per chain: seed with parent global transform,
// recompute local ht inline from dofs (no 12MB scratch round-trip), 15 serial
// products, scatter translations via kin_id.
// ---------------------------------------------------------------------------
__global__ void k3_sidechains(const float* __restrict__ dofs,
                              const int* __restrict__ kin_id,
                              float* __restrict__ out) {
    int c = blockIdx.x * blockDim.x + threadIdx.x;
    if (c >= B_CHAIN) return;

    float G[12];
    load12(g_hg0 + (c + 1) * 12, G);   // parent = c+1

    int node = GEN1_BASE + c * S_SIDE;
#pragma unroll 1
    for (int j = 0; j < S_SIDE; j++, node++) {
        float4 dv = ((const float4*)dofs)[node - 1];
        float M[12], T[12];
        make_bond(dv.x, dv.y, dv.z, dv.w, M);   // all gen1 atoms are bond-type
        aff_mul(G, M, T);
#pragma unroll
        for (int k = 0; k < 12; k++) G[k] = T[k];
        int kid = kin_id[node];
        out[kid * 3 + 0] = G[9];
        out[kid * 3 + 1] = G[10];
        out[kid * 3 + 2] = G[11];
    }
}

extern "C" void kernel_launch(void* const* d_in, const int* in_sizes, int n_in,
                              void* d_out, int out_size) {
    const float* dofs   = (const float*)d_in[0];
    const int*   kin_id = (const int*)d_in[8];
    float*       out    = (float*)d_out;

    k1_backbone_ht<<<(B_CHAIN + 255) / 256, 256>>>(dofs);
    k2_backbone_scan<<<1, NCHUNK>>>(kin_id, out);
    k3_sidechains<<<(B_CHAIN + 127) / 128, 128>>>(dofs, kin_id, out);
}

// round 3
// speedup vs baseline: 8.1339x; 8.1339x over previous
#include <cuda_runtime.h>

#define B_CHAIN 16384
#define S_SIDE 15
#define NATM (1 + B_CHAIN + B_CHAIN * S_SIDE)
#define GEN1_BASE (1 + B_CHAIN)

#define TPB_A 256              // atoms per block in backbone scan
#define NBLK_A (B_CHAIN / TPB_A)   // 64

// Scratch (static __device__ arrays — no allocation).
__device__ __align__(16) float g_scan[(B_CHAIN + 1) * 12];  // per-atom inclusive-within-block
__device__ __align__(16) float g_blk[NBLK_A * 12];          // per-block totals
__device__ __align__(16) float g_hg0[(B_CHAIN + 1) * 12];   // global transforms of backbone atoms

// Affine 3x4: m[0..8] row-major rotation, m[9..11] translation. c = a*b (a earlier).
__device__ __forceinline__ void aff_mul(const float a[12], const float b[12], float c[12]) {
#pragma unroll
    for (int i = 0; i < 3; i++) {
        float a0 = a[i * 3 + 0], a1 = a[i * 3 + 1], a2 = a[i * 3 + 2];
        float t  = a[9 + i];
        c[i * 3 + 0] = a0 * b[0] + a1 * b[3] + a2 * b[6];
        c[i * 3 + 1] = a0 * b[1] + a1 * b[4] + a2 * b[7];
        c[i * 3 + 2] = a0 * b[2] + a1 * b[5] + a2 * b[8];
        c[9 + i]     = a0 * b[9] + a1 * b[10] + a2 * b[11] + t;
    }
}

__device__ __forceinline__ void aff_identity(float m[12]) {
#pragma unroll
    for (int k = 0; k < 12; k++) m[k] = 0.0f;
    m[0] = m[4] = m[8] = 1.0f;
}

// ht_bond = Rx(p)*Rz(t)*T(d,0,0)*Rx(c), collapsed. Precise trig (backbone).
__device__ __forceinline__ void make_bond(float p, float t, float d, float c, float m[12]) {
    float sp, cp, st, ct, sc, cc;
    sincosf(p, &sp, &cp);
    sincosf(t, &st, &ct);
    sincosf(c, &sc, &cc);
    m[0] = ct;        m[1] = -st * cc;               m[2] = st * sc;
    m[3] = cp * st;   m[4] = cp * ct * cc - sp * sc; m[5] = -cp * ct * sc - sp * cc;
    m[6] = sp * st;   m[7] = sp * ct * cc + cp * sc; m[8] = -sp * ct * sc + cp * cc;
    m[9] = ct * d;    m[10] = cp * st * d;           m[11] = sp * st * d;
}

// Fast-trig variant (side chains: 15-product chains, error doesn't accumulate).
__device__ __forceinline__ void make_bond_fast(float p, float t, float d, float c, float m[12]) {
    float sp, cp, st, ct, sc, cc;
    __sincosf(p, &sp, &cp);
    __sincosf(t, &st, &ct);
    __sincosf(c, &sc, &cc);
    m[0] = ct;        m[1] = -st * cc;               m[2] = st * sc;
    m[3] = cp * st;   m[4] = cp * ct * cc - sp * sc; m[5] = -cp * ct * sc - sp * cc;
    m[6] = sp * st;   m[7] = sp * ct * cc + cp * sc; m[8] = -sp * ct * sc + cp * cc;
    m[9] = ct * d;    m[10] = cp * st * d;           m[11] = sp * st * d;
}

__device__ __forceinline__ void make_ht(int atom, float4 dv, float m[12]) {
    if (atom == 1) {   // jump node: T(d0,d1,d2)*Rx(d3)
        float sc, cc;
        sincosf(dv.w, &sc, &cc);
        m[0] = 1.f; m[1] = 0.f; m[2] = 0.f;
        m[3] = 0.f; m[4] = cc;  m[5] = -sc;
        m[6] = 0.f; m[7] = sc;  m[8] = cc;
        m[9] = dv.x; m[10] = dv.y; m[11] = dv.z;
    } else {
        make_bond(dv.x, dv.y, dv.z, dv.w, m);
    }
}

__device__ __forceinline__ void store12(float* dst, const float m[12]) {
    float4* d4 = (float4*)dst;
    d4[0] = make_float4(m[0], m[1], m[2], m[3]);
    d4[1] = make_float4(m[4], m[5], m[6], m[7]);
    d4[2] = make_float4(m[8], m[9], m[10], m[11]);
}

__device__ __forceinline__ void load12(const float* src, float m[12]) {
    const float4* s4 = (const float4*)src;
    float4 a = s4[0], b = s4[1], c = s4[2];
    m[0] = a.x; m[1] = a.y; m[2] = a.z; m[3] = a.w;
    m[4] = b.x; m[5] = b.y; m[6] = b.z; m[7] = b.w;
    m[8] = c.x; m[9] = c.y; m[10] = c.z; m[11] = c.w;
}

// ---------------------------------------------------------------------------
// kA: build backbone ht inline + per-block inclusive KS scan over 256 atoms.
// Writes g_scan (per-atom inclusive within block) and g_blk (block total).
// ---------------------------------------------------------------------------
__global__ void __launch_bounds__(TPB_A) kA_block_scan(const float* __restrict__ dofs) {
    __shared__ float s[12 * TPB_A];   // component-major
    int t = threadIdx.x;
    int atom = blockIdx.x * TPB_A + t + 1;

    float4 dv = ((const float4*)dofs)[atom - 1];
    float P[12];
    make_ht(atom, dv, P);

#pragma unroll
    for (int k = 0; k < 12; k++) s[k * TPB_A + t] = P[k];
    __syncthreads();

    // Kogge-Stone inclusive scan (8 steps)
    for (int d = 1; d < TPB_A; d <<= 1) {
        float L[12];
        bool act = (t >= d);
        if (act) {
#pragma unroll
            for (int k = 0; k < 12; k++) L[k] = s[k * TPB_A + (t - d)];
        }
        __syncthreads();
        if (act) {
            float T[12];
            aff_mul(L, P, T);
#pragma unroll
            for (int k = 0; k < 12; k++) { P[k] = T[k]; s[k * TPB_A + t] = T[k]; }
        }
        __syncthreads();
    }

    store12(g_scan + atom * 12, P);
    if (t == TPB_A - 1) store12(g_blk + blockIdx.x * 12, P);
}

// ---------------------------------------------------------------------------
// kC: every block redundantly scans the 64 block totals in shared (exclusive
// prefix for its own block), then applies it: G = pre * scan[atom].
// Writes g_hg0 + scattered backbone coordinates.
// ---------------------------------------------------------------------------
__global__ void __launch_bounds__(TPB_A) kC_apply(const int* __restrict__ kin_id,
                                                  float* __restrict__ out) {
    __shared__ float sb[12 * NBLK_A];   // 3KB
    int t = threadIdx.x;
    int b = blockIdx.x;
    int atom = b * TPB_A + t + 1;

    float Pb[12];
    if (t < NBLK_A) {
        load12(g_blk + t * 12, Pb);
#pragma unroll
        for (int k = 0; k < 12; k++) sb[k * NBLK_A + t] = Pb[k];
    }
    __syncthreads();

    for (int d = 1; d < NBLK_A; d <<= 1) {
        float L[12];
        bool act = (t < NBLK_A) && (t >= d);
        if (act) {
#pragma unroll
            for (int k = 0; k < 12; k++) L[k] = sb[k * NBLK_A + (t - d)];
        }
        __syncthreads();
        if (act) {
            float T[12];
            aff_mul(L, Pb, T);
#pragma unroll
            for (int k = 0; k < 12; k++) { Pb[k] = T[k]; sb[k * NBLK_A + t] = T[k]; }
        }
        __syncthreads();
    }

    // exclusive prefix for this block
    float pre[12];
    if (b == 0) {
        aff_identity(pre);
    } else {
#pragma unroll
        for (int k = 0; k < 12; k++) pre[k] = sb[k * NBLK_A + (b - 1)];
    }

    float Sv[12], G[12];
    load12(g_scan + atom * 12, Sv);
    aff_mul(pre, Sv, G);
    store12(g_hg0 + atom * 12, G);

    int kid = kin_id[atom];
    out[kid * 3 + 0] = G[9];
    out[kid * 3 + 1] = G[10];
    out[kid * 3 + 2] = G[11];
}

// ---------------------------------------------------------------------------
// kD: side chains. 16 lanes per chain (2 chains per warp). Lane 0 holds the
// parent's global transform; lanes 1..15 build one bond matrix each.
// Inclusive segmented Kogge-Stone over 16 lanes via shfl_up(width=16).
// Grid is exact: B_CHAIN*16 threads.
// ---------------------------------------------------------------------------
__global__ void __launch_bounds__(256) kD_sidechains(const float* __restrict__ dofs,
                                                     const int* __restrict__ kin_id,
                                                     float* __restrict__ out) {
    int g = blockIdx.x * blockDim.x + threadIdx.x;
    int c  = g >> 4;        // chain index 0..B_CHAIN-1
    int sl = g & 15;        // sub-lane within 16-wide segment

    float P[12];
    int node = 0;
    if (sl == 0) {
        load12(g_hg0 + (c + 1) * 12, P);          // parent global transform
    } else {
        node = GEN1_BASE + c * S_SIDE + (sl - 1);
        float4 dv = ((const float4*)dofs)[node - 1];
        make_bond_fast(dv.x, dv.y, dv.z, dv.w, P);
    }

#pragma unroll
    for (int d = 1; d < 16; d <<= 1) {
        float L[12];
#pragma unroll
        for (int k = 0; k < 12; k++)
            L[k] = __shfl_up_sync(0xffffffffu, P[k], d, 16);
        if (sl >= d) {
            float T[12];
            aff_mul(L, P, T);
#pragma unroll
            for (int k = 0; k < 12; k++) P[k] = T[k];
        }
    }

    if (sl > 0) {
        int kid = kin_id[node];
        out[kid * 3 + 0] = P[9];
        out[kid * 3 + 1] = P[10];
        out[kid * 3 + 2] = P[11];
    }
}

extern "C" void kernel_launch(void* const* d_in, const int* in_sizes, int n_in,
                              void* d_out, int out_size) {
    const float* dofs   = (const float*)d_in[0];
    const int*   kin_id = (const int*)d_in[8];
    float*       out    = (float*)d_out;

    kA_block_scan<<<NBLK_A, TPB_A>>>(dofs);
    kC_apply<<<NBLK_A, TPB_A>>>(kin_id, out);
    kD_sidechains<<<(B_CHAIN * 16) / 256, 256>>>(dofs, kin_id, out);
}

// round 4
// speedup vs baseline: 8.8748x; 1.0911x over previous
#include <cuda_runtime.h>

#define B_CHAIN 16384
#define S_SIDE 15
#define NATM (1 + B_CHAIN + B_CHAIN * S_SIDE)
#define GEN1_BASE (1 + B_CHAIN)

#define TPB_A 256
#define NBLK_A (B_CHAIN / TPB_A)   // 64

// Scratch (static __device__ arrays — no allocation).
__device__ __align__(16) float g_scan[(B_CHAIN + 1) * 12];  // inclusive-within-K1-block
__device__ __align__(16) float g_blk[NBLK_A * 12];          // K1 block totals

// Affine 3x4: m[0..8] row-major rotation, m[9..11] translation. c = a*b (a earlier in chain).
__device__ __forceinline__ void aff_mul(const float a[12], const float b[12], float c[12]) {
#pragma unroll
    for (int i = 0; i < 3; i++) {
        float a0 = a[i * 3 + 0], a1 = a[i * 3 + 1], a2 = a[i * 3 + 2];
        float t  = a[9 + i];
        c[i * 3 + 0] = a0 * b[0] + a1 * b[3] + a2 * b[6];
        c[i * 3 + 1] = a0 * b[1] + a1 * b[4] + a2 * b[7];
        c[i * 3 + 2] = a0 * b[2] + a1 * b[5] + a2 * b[8];
        c[9 + i]     = a0 * b[9] + a1 * b[10] + a2 * b[11] + t;
    }
}

// ht_bond = Rx(p)*Rz(t)*T(d,0,0)*Rx(c), collapsed. Precise trig (backbone: error
// random-walks over 16K products).
__device__ __forceinline__ void make_bond(float p, float t, float d, float c, float m[12]) {
    float sp, cp, st, ct, sc, cc;
    sincosf(p, &sp, &cp);
    sincosf(t, &st, &ct);
    sincosf(c, &sc, &cc);
    m[0] = ct;        m[1] = -st * cc;               m[2] = st * sc;
    m[3] = cp * st;   m[4] = cp * ct * cc - sp * sc; m[5] = -cp * ct * sc - sp * cc;
    m[6] = sp * st;   m[7] = sp * ct * cc + cp * sc; m[8] = -sp * ct * sc + cp * cc;
    m[9] = ct * d;    m[10] = cp * st * d;           m[11] = sp * st * d;
}

// Fast-trig variant (side chains: 15-product chains, no accumulation).
__device__ __forceinline__ void make_bond_fast(float p, float t, float d, float c, float m[12]) {
    float sp, cp, st, ct, sc, cc;
    __sincosf(p, &sp, &cp);
    __sincosf(t, &st, &ct);
    __sincosf(c, &sc, &cc);
    m[0] = ct;        m[1] = -st * cc;               m[2] = st * sc;
    m[3] = cp * st;   m[4] = cp * ct * cc - sp * sc; m[5] = -cp * ct * sc - sp * cc;
    m[6] = sp * st;   m[7] = sp * ct * cc + cp * sc; m[8] = -sp * ct * sc + cp * cc;
    m[9] = ct * d;    m[10] = cp * st * d;           m[11] = sp * st * d;
}

__device__ __forceinline__ void make_ht(int atom, float4 dv, float m[12]) {
    if (atom == 1) {   // jump node: T(d0,d1,d2)*Rx(d3)
        float sc, cc;
        sincosf(dv.w, &sc, &cc);
        m[0] = 1.f; m[1] = 0.f; m[2] = 0.f;
        m[3] = 0.f; m[4] = cc;  m[5] = -sc;
        m[6] = 0.f; m[7] = sc;  m[8] = cc;
        m[9] = dv.x; m[10] = dv.y; m[11] = dv.z;
    } else {
        make_bond(dv.x, dv.y, dv.z, dv.w, m);
    }
}

__device__ __forceinline__ void store12(float* dst, const float m[12]) {
    float4* d4 = (float4*)dst;
    d4[0] = make_float4(m[0], m[1], m[2], m[3]);
    d4[1] = make_float4(m[4], m[5], m[6], m[7]);
    d4[2] = make_float4(m[8], m[9], m[10], m[11]);
}

__device__ __forceinline__ void load12(const float* src, float m[12]) {
    const float4* s4 = (const float4*)src;
    float4 a = s4[0], b = s4[1], c = s4[2];
    m[0] = a.x; m[1] = a.y; m[2] = a.z; m[3] = a.w;
    m[4] = b.x; m[5] = b.y; m[6] = b.z; m[7] = b.w;
    m[8] = c.x; m[9] = c.y; m[10] = c.z; m[11] = c.w;
}

// Warp-level inclusive Kogge-Stone over `width` lanes (power of 2 <= 32).
template <int WIDTH>
__device__ __forceinline__ void warp_scan(float P[12], int lane) {
#pragma unroll
    for (int d = 1; d < WIDTH; d <<= 1) {
        float L[12];
#pragma unroll
        for (int k = 0; k < 12; k++)
            L[k] = __shfl_up_sync(0xffffffffu, P[k], d, 32);
        if (lane >= d) {
            float T[12];
            aff_mul(L, P, T);
#pragma unroll
            for (int k = 0; k < 12; k++) P[k] = T[k];
        }
    }
}

// ---------------------------------------------------------------------------
// K1: build backbone ht + block-inclusive scan (warp shfl scan, 2 barriers).
// ---------------------------------------------------------------------------
__global__ void __launch_bounds__(TPB_A) kA_block_scan(const float* __restrict__ dofs) {
    __shared__ float wt[12 * 8];   // per-warp totals (component-minor, 12 per warp)
    int t = threadIdx.x;
    int w = t >> 5, l = t & 31;
    int atom = blockIdx.x * TPB_A + t + 1;

    float4 dv = ((const float4*)dofs)[atom - 1];
    float P[12];
    make_ht(atom, dv, P);

    // 5-step warp scan, no barriers
    warp_scan<32>(P, l);

    if (l == 31) {
#pragma unroll
        for (int k = 0; k < 12; k++) wt[w * 12 + k] = P[k];
    }
    __syncthreads();

    // warp 0 scans the 8 warp totals (lanes 0..7)
    if (w == 0 && l < 8) {
        float Q[12];
#pragma unroll
        for (int k = 0; k < 12; k++) Q[k] = wt[l * 12 + k];
#pragma unroll
        for (int d = 1; d < 8; d <<= 1) {
            float L[12];
#pragma unroll
            for (int k = 0; k < 12; k++)
                L[k] = __shfl_up_sync(0x000000ffu, Q[k], d, 32);
            if (l >= d) {
                float T[12];
                aff_mul(L, Q, T);
#pragma unroll
                for (int k = 0; k < 12; k++) Q[k] = T[k];
            }
        }
#pragma unroll
        for (int k = 0; k < 12; k++) wt[l * 12 + k] = Q[k];
    }
    __syncthreads();

    // apply exclusive warp-prefix
    if (w > 0) {
        float E[12], T[12];
#pragma unroll
        for (int k = 0; k < 12; k++) E[k] = wt[(w - 1) * 12 + k];
        aff_mul(E, P, T);
#pragma unroll
        for (int k = 0; k < 12; k++) P[k] = T[k];
    }

    store12(g_scan + atom * 12, P);
    if (t == TPB_A - 1) store12(g_blk + blockIdx.x * 12, P);
}

// ---------------------------------------------------------------------------
// K2 (fused): every block redundantly scans the 64 block totals (2-warp shfl
// scan), then each 16-lane segment handles one side chain. Lane 0 computes
// the parent backbone atom's global transform (pre * g_scan[parent]) and
// emits its coordinate; lanes 1..15 build bond matrices; 4-step segmented
// shfl scan; all lanes emit coordinates. Covers ALL NATM-1 output atoms
// (parents c+1 are exactly backbone atoms 1..B_CHAIN).
// ---------------------------------------------------------------------------
__global__ void __launch_bounds__(256) kE_fused(const float* __restrict__ dofs,
                                               const int* __restrict__ kin_id,
                                               float* __restrict__ out) {
    __shared__ float sb[NBLK_A * 12];   // inclusive scan of the 64 K1-block totals
    int t = threadIdx.x;

    // --- redundant scan of 64 block totals (threads 0..63 = 2 warps) ---
    float Q[12];
    if (t < NBLK_A) {
        load12(g_blk + t * 12, Q);
        warp_scan<32>(Q, t & 31);
#pragma unroll
        for (int k = 0; k < 12; k++) sb[t * 12 + k] = Q[k];
    }
    __syncthreads();
    if (t >= 32 && t < 64) {
        float E[12], T[12];
#pragma unroll
        for (int k = 0; k < 12; k++) E[k] = sb[31 * 12 + k];
        aff_mul(E, Q, T);
#pragma unroll
        for (int k = 0; k < 12; k++) sb[t * 12 + k] = T[k];
    }
    __syncthreads();

    // --- side chains, 16 lanes per chain ---
    int g = blockIdx.x * blockDim.x + t;
    int c  = g >> 4;        // chain 0..B_CHAIN-1
    int sl = g & 15;

    float P[12];
    int node;
    if (sl == 0) {
        node = c + 1;                       // parent backbone atom
        float Sv[12];
        load12(g_scan + node * 12, Sv);
        int kb = c >> 8;                    // K1 block of parent atom
        if (kb == 0) {
#pragma unroll
            for (int k = 0; k < 12; k++) P[k] = Sv[k];
        } else {
            float pre[12];
#pragma unroll
            for (int k = 0; k < 12; k++) pre[k] = sb[(kb - 1) * 12 + k];
            aff_mul(pre, Sv, P);
        }
    } else {
        node = GEN1_BASE + c * S_SIDE + (sl - 1);
        float4 dv = ((const float4*)dofs)[node - 1];
        make_bond_fast(dv.x, dv.y, dv.z, dv.w, P);
    }

    // segmented 4-step scan over the 16-lane segment
#pragma unroll
    for (int d = 1; d < 16; d <<= 1) {
        float L[12];
#pragma unroll
        for (int k = 0; k < 12; k++)
            L[k] = __shfl_up_sync(0xffffffffu, P[k], d, 16);
        if (sl >= d) {
            float T[12];
            aff_mul(L, P, T);
#pragma unroll
            for (int k = 0; k < 12; k++) P[k] = T[k];
        }
    }

    int kid = kin_id[node];
    out[kid * 3 + 0] = P[9];
    out[kid * 3 + 1] = P[10];
    out[kid * 3 + 2] = P[11];
}

extern "C" void kernel_launch(void* const* d_in, const int* in_sizes, int n_in,
                              void* d_out, int out_size) {
    const float* dofs   = (const float*)d_in[0];
    const int*   kin_id = (const int*)d_in[8];
    float*       out    = (float*)d_out;

    kA_block_scan<<<NBLK_A, TPB_A>>>(dofs);
    kE_fused<<<(B_CHAIN * 16) / 256, 256>>>(dofs, kin_id, out);
}